// round 2
// baseline (speedup 1.0000x reference)
#include <cuda_runtime.h>
#include <cuda_bf16.h>
#include <cstdint>

#define T_LEN 512
#define BB    64
#define EMBD  256
#define HD    256
#define G4    1024
#define LL    9
#define NCTA  128

typedef unsigned long long ull;

// ------------------------- device scratch ----------------------------------
__device__ float g_xg[2][T_LEN][G4][BB];   // 256 MB: pre-activations, b fastest
__device__ float g_h [2][T_LEN][HD][BB];   // 64 MB : hidden states (scan order)
__device__ float g_em[BB][T_LEN][LL];
__device__ float g_res[BB];
__device__ unsigned g_cnt = 0;
__device__ unsigned g_gen = 0;

// ------------------------- helpers -----------------------------------------
__device__ __forceinline__ ull pack2(float a, float b) {
    ull r; asm("mov.b64 %0, {%1,%2};" : "=l"(r) : "f"(a), "f"(b)); return r;
}
__device__ __forceinline__ void unpack2(ull v, float& a, float& b) {
    asm("mov.b64 {%0,%1}, %2;" : "=f"(a), "=f"(b) : "l"(v));
}
__device__ __forceinline__ ull fma2(ull a, ull b, ull c) {
    ull d; asm("fma.rn.f32x2 %0, %1, %2, %3;" : "=l"(d) : "l"(a), "l"(b), "l"(c));
    return d;
}
__device__ __forceinline__ float sigf(float x) { return 1.0f / (1.0f + expf(-x)); }

// ===========================================================================
// K1: xg[d][t][row][b] = W_ih x_t + b_ih + b_hh.  grid (8,512,2) x 256 thr.
// ===========================================================================
__global__ void k_xg(const int* __restrict__ ids, const float* __restrict__ emb,
                     const float* __restrict__ wif, const float* __restrict__ bif,
                     const float* __restrict__ bhf,
                     const float* __restrict__ wib, const float* __restrict__ bib,
                     const float* __restrict__ bhb)
{
    __shared__ float A_s[32][64];      // k-chunk x batch
    __shared__ ull   W_s[128][33];     // duplicated {w,w} pairs, padded

    const int d  = blockIdx.z;
    const int t  = blockIdx.y;
    const int R  = blockIdx.x * 128;
    const int tid = threadIdx.x;
    const int tp = (d == 0) ? t : (T_LEN - 1 - t);
    const float* w_ih = d ? wib : wif;
    const float* bi   = d ? bib : bif;
    const float* bh   = d ? bhb : bhf;

    const int rg = tid >> 3, bg = tid & 7;
    const int r0 = rg * 4,  b0 = bg * 8;

    // per-thread fixed roles for loading
    const int lb  = tid & 63;           // batch for A gather
    const int seg = tid >> 6;           // k-subsegment 0..3
    const float* erow = emb + (size_t)ids[lb * T_LEN + tp] * EMBD;
    const int lr = tid >> 1, lh = tid & 1;   // W load: row, half

    ull acc[4][4];
#pragma unroll
    for (int rr = 0; rr < 4; rr++) {
        float bs = bi[R + r0 + rr] + bh[R + r0 + rr];
        ull p = pack2(bs, bs);
#pragma unroll
        for (int q = 0; q < 4; q++) acc[rr][q] = p;
    }

    for (int cc = 0; cc < 8; cc++) {           // k chunks of 32
        __syncthreads();
        {   // A gather: 8 floats per thread
            float4 v0 = *(const float4*)(erow + cc * 32 + seg * 8);
            float4 v1 = *(const float4*)(erow + cc * 32 + seg * 8 + 4);
            int k = seg * 8;
            A_s[k+0][lb] = v0.x; A_s[k+1][lb] = v0.y; A_s[k+2][lb] = v0.z; A_s[k+3][lb] = v0.w;
            A_s[k+4][lb] = v1.x; A_s[k+5][lb] = v1.y; A_s[k+6][lb] = v1.z; A_s[k+7][lb] = v1.w;
        }
        {   // W chunk: 16 floats per thread, store duplicated pairs
            const float4* w4 = (const float4*)(w_ih + (size_t)(R + lr) * EMBD + cc * 32 + lh * 16);
#pragma unroll
            for (int j = 0; j < 4; j++) {
                float4 v = w4[j];
                int k = lh * 16 + j * 4;
                W_s[lr][k+0] = pack2(v.x, v.x);
                W_s[lr][k+1] = pack2(v.y, v.y);
                W_s[lr][k+2] = pack2(v.z, v.z);
                W_s[lr][k+3] = pack2(v.w, v.w);
            }
        }
        __syncthreads();
#pragma unroll 8
        for (int kk = 0; kk < 32; kk++) {
            const ull* ap = (const ull*)&A_s[kk][b0];
            ull a0 = ap[0], a1 = ap[1], a2 = ap[2], a3 = ap[3];
#pragma unroll
            for (int rr = 0; rr < 4; rr++) {
                ull wv = W_s[r0 + rr][kk];
                acc[rr][0] = fma2(wv, a0, acc[rr][0]);
                acc[rr][1] = fma2(wv, a1, acc[rr][1]);
                acc[rr][2] = fma2(wv, a2, acc[rr][2]);
                acc[rr][3] = fma2(wv, a3, acc[rr][3]);
            }
        }
    }
#pragma unroll
    for (int rr = 0; rr < 4; rr++) {
        ull* op = (ull*)&g_xg[d][t][R + r0 + rr][b0];
        op[0] = acc[rr][0]; op[1] = acc[rr][1]; op[2] = acc[rr][2]; op[3] = acc[rr][3];
    }
}

// ===========================================================================
// K2: recurrence. 128 persistent CTAs x 128 thr. CTA=(dir, 4 hidden units).
// ===========================================================================
__device__ __forceinline__ void grid_barrier()
{
    __syncthreads();
    if (threadIdx.x == 0) {
        unsigned gen0 = *(volatile unsigned*)&g_gen;
        __threadfence();
        if (atomicAdd(&g_cnt, 1u) == NCTA - 1u) {
            g_cnt = 0;
            __threadfence();
            atomicAdd(&g_gen, 1u);
        } else {
            while (*(volatile unsigned*)&g_gen == gen0) { __nanosleep(40); }
        }
        __threadfence();
    }
    __syncthreads();
}

__global__ void k_lstm(const float* __restrict__ whhf, const float* __restrict__ whhb)
{
    extern __shared__ ull smu[];
    ull* W2  = smu;          // [16][256] duplicated pairs (32 KB)
    ull* h_u = smu + 4096;   // [256][32] h pairs          (64 KB)

    const int cta = blockIdx.x;
    const int d = cta >> 6, s = cta & 63;
    const int tid = threadIdx.x;
    const int w = tid >> 5, l = tid & 31;
    const int u = (s << 2) + w;
    const float* whh = d ? whhb : whhf;

    for (int e = tid; e < 16 * 256; e += 128) {
        int r = e >> 8, k = e & 255;
        float v = whh[(size_t)((r >> 2) * 256 + (s << 2) + (r & 3)) * 256 + k];
        W2[e] = pack2(v, v);
    }
    const ull* wb0 = W2 + ((0 * 4 + w) << 8);
    const ull* wb1 = W2 + ((1 * 4 + w) << 8);
    const ull* wb2 = W2 + ((2 * 4 + w) << 8);
    const ull* wb3 = W2 + ((3 * 4 + w) << 8);

    float c0 = 0.f, c1 = 0.f;

    for (int t = 0; t < T_LEN; t++) {
        ull a0 = *(const ull*)&g_xg[d][t][      u][l * 2];
        ull a1 = *(const ull*)&g_xg[d][t][256 + u][l * 2];
        ull a2 = *(const ull*)&g_xg[d][t][512 + u][l * 2];
        ull a3 = *(const ull*)&g_xg[d][t][768 + u][l * 2];

        if (t == 0) {
            for (int j = tid; j < 8192; j += 128) h_u[j] = 0ULL;
        } else {
            const ull* src = (const ull*)&g_h[d][t - 1][0][0];
#pragma unroll 8
            for (int j = tid; j < 8192; j += 128) h_u[j] = src[j];
        }
        __syncthreads();

#pragma unroll 4
        for (int k = 0; k < 256; k++) {
            ull hp = h_u[(k << 5) + l];
            a0 = fma2(wb0[k], hp, a0);
            a1 = fma2(wb1[k], hp, a1);
            a2 = fma2(wb2[k], hp, a2);
            a3 = fma2(wb3[k], hp, a3);
        }

        float i0,i1,f0,f1,gg0,gg1,o0,o1;
        unpack2(a0,i0,i1); unpack2(a1,f0,f1); unpack2(a2,gg0,gg1); unpack2(a3,o0,o1);
        c0 = sigf(f0)*c0 + sigf(i0)*tanhf(gg0);
        c1 = sigf(f1)*c1 + sigf(i1)*tanhf(gg1);
        float h0 = sigf(o0)*tanhf(c0);
        float h1 = sigf(o1)*tanhf(c1);
        *(ull*)&g_h[d][t][u][l * 2] = pack2(h0, h1);

        grid_barrier();
    }
}

// ===========================================================================
// K3: emissions[b][t][l] = [hf;hb] . w_cls[l] + b_cls[l].  grid T x 64 thr.
// ===========================================================================
__global__ void k_emis(const float* __restrict__ w_cls, const float* __restrict__ b_cls)
{
    __shared__ float wc[LL][512];
    const int tid = threadIdx.x, t = blockIdx.x;
    for (int i = tid; i < LL * 512; i += 64) wc[i >> 9][i & 511] = w_cls[i];
    __syncthreads();

    const int b = tid;
    const float* hf = &g_h[0][t][0][0] + b;
    const float* hb = &g_h[1][T_LEN - 1 - t][0][0] + b;
    float acc[LL];
#pragma unroll
    for (int ll = 0; ll < LL; ll++) acc[ll] = b_cls[ll];
    for (int u = 0; u < 256; u++) {
        float hv = hf[u << 6];
#pragma unroll
        for (int ll = 0; ll < LL; ll++) acc[ll] += hv * wc[ll][u];
    }
    for (int u = 0; u < 256; u++) {
        float hv = hb[u << 6];
#pragma unroll
        for (int ll = 0; ll < LL; ll++) acc[ll] += hv * wc[ll][256 + u];
    }
#pragma unroll
    for (int ll = 0; ll < LL; ll++) g_em[b][t][ll] = acc[ll];
}

// ===========================================================================
// K4: CRF numerator + forward per batch (one warp / batch). grid 8 x 256 thr.
// ===========================================================================
__global__ void k_crf(const int* __restrict__ labels, const int* __restrict__ mask,
                      const float* __restrict__ trans, const float* __restrict__ start,
                      const float* __restrict__ endv)
{
    const int warp = threadIdx.x >> 5, lane = threadIdx.x & 31;
    const int b = blockIdx.x * 8 + warp;
    if (b >= BB) return;
    const float NEG = -1e30f;
    const int* lab = labels + b * T_LEN;
    const int* msk = mask   + b * T_LEN;
    const float* em = &g_em[b][0][0];

    // numerator partials + mask sum (lane-strided, warp-reduced)
    float numl = 0.f; int msum = 0;
    for (int t = lane; t < T_LEN; t += 32) msum += msk[t];
    for (int t = 1 + lane; t < T_LEN; t += 32) {
        float mf = (float)msk[t];
        numl += mf * (trans[lab[t - 1] * LL + lab[t]] + em[t * LL + lab[t]]);
    }
#pragma unroll
    for (int o = 16; o; o >>= 1) {
        numl += __shfl_xor_sync(0xFFFFFFFFu, numl, o);
        msum += __shfl_xor_sync(0xFFFFFFFFu, msum, o);
    }

    // forward algorithm: lane j holds alpha_j (j<9)
    float trc[LL];
#pragma unroll
    for (int i = 0; i < LL; i++) trc[i] = (lane < LL) ? trans[i * LL + lane] : 0.f;
    float alpha = (lane < LL) ? start[lane] + em[lane] : NEG;

    for (int t = 1; t < T_LEN; t++) {
        float emj = (lane < LL) ? em[t * LL + lane] : 0.f;
        float tv[LL], m = NEG;
#pragma unroll
        for (int i = 0; i < LL; i++) {
            float ai = __shfl_sync(0xFFFFFFFFu, alpha, i);
            tv[i] = ai + trc[i];
            m = fmaxf(m, tv[i]);
        }
        float ss = 0.f;
#pragma unroll
        for (int i = 0; i < LL; i++) ss += __expf(tv[i] - m);
        float nxt = m + __logf(ss) + emj;
        if (lane < LL && msk[t]) alpha = nxt;
    }

    float v = (lane < LL) ? alpha + endv[lane] : NEG;
    float m = v;
#pragma unroll
    for (int o = 16; o; o >>= 1) m = fmaxf(m, __shfl_xor_sync(0xFFFFFFFFu, m, o));
    float sv = __expf(v - m);
#pragma unroll
    for (int o = 16; o; o >>= 1) sv += __shfl_xor_sync(0xFFFFFFFFu, sv, o);
    float logZ = m + __logf(sv);

    if (lane == 0) {
        int lab0 = lab[0];
        int lastt = msum - 1;
        float num = numl + start[lab0] + em[lab0] + endv[lab[lastt]];
        g_res[b] = num - logZ;
    }
}

__global__ void k_final(float* out)
{
    const int tid = threadIdx.x;
    float v = g_res[tid];
#pragma unroll
    for (int o = 16; o; o >>= 1) v += __shfl_xor_sync(0xFFFFFFFFu, v, o);
    __shared__ float sred[2];
    if ((tid & 31) == 0) sred[tid >> 5] = v;
    __syncthreads();
    if (tid == 0) out[0] = -(sred[0] + sred[1]) / 64.0f;
}

// ===========================================================================
extern "C" void kernel_launch(void* const* d_in, const int* in_sizes, int n_in,
                              void* d_out, int out_size)
{
    const int*   ids   = (const int*)  d_in[0];
    const int*   msk   = (const int*)  d_in[1];
    const int*   lab   = (const int*)  d_in[2];
    const float* emb   = (const float*)d_in[3];
    const float* wif   = (const float*)d_in[4];
    const float* whf   = (const float*)d_in[5];
    const float* bif   = (const float*)d_in[6];
    const float* bhf   = (const float*)d_in[7];
    const float* wib   = (const float*)d_in[8];
    const float* whb   = (const float*)d_in[9];
    const float* bib   = (const float*)d_in[10];
    const float* bhb   = (const float*)d_in[11];
    const float* wcls  = (const float*)d_in[12];
    const float* bcls  = (const float*)d_in[13];
    const float* trans = (const float*)d_in[14];
    const float* start = (const float*)d_in[15];
    const float* endv  = (const float*)d_in[16];

    cudaFuncSetAttribute(k_lstm, cudaFuncAttributeMaxDynamicSharedMemorySize, 98304);

    k_xg  <<<dim3(8, T_LEN, 2), 256>>>(ids, emb, wif, bif, bhf, wib, bib, bhb);
    k_lstm<<<NCTA, 128, 98304>>>(whf, whb);
    k_emis<<<T_LEN, 64>>>(wcls, bcls);
    k_crf <<<8, 256>>>(lab, msk, trans, start, endv);
    k_final<<<1, 64>>>((float*)d_out);
}

// round 3
// speedup vs baseline: 1.8842x; 1.8842x over previous
#include <cuda_runtime.h>
#include <cuda_bf16.h>
#include <cstdint>

#define T_LEN 512
#define BB    64
#define EMBD  256
#define HD    256
#define G4    1024
#define LL    9
#define NCTA  128

typedef unsigned long long ull;

// ------------------------- device scratch ----------------------------------
__device__ float g_xg[2][T_LEN][G4][BB];   // pre-activations, b fastest
__device__ float g_h [2][T_LEN][HD][BB];   // hidden states
__device__ float g_em[BB][T_LEN][LL];
__device__ float g_res[BB];
__device__ unsigned g_ctr[8][32];          // [dir*4+grp][pad] arrival counters

// ------------------------- helpers -----------------------------------------
__device__ __forceinline__ ull pack2(float a, float b) {
    ull r; asm("mov.b64 %0, {%1,%2};" : "=l"(r) : "f"(a), "f"(b)); return r;
}
__device__ __forceinline__ void unpack2(ull v, float& a, float& b) {
    asm("mov.b64 {%0,%1}, %2;" : "=f"(a), "=f"(b) : "l"(v));
}
__device__ __forceinline__ ull fma2(ull a, ull b, ull c) {
    ull d; asm("fma.rn.f32x2 %0, %1, %2, %3;" : "=l"(d) : "l"(a), "l"(b), "l"(c));
    return d;
}
__device__ __forceinline__ float fsig(float x) {
    return __fdividef(1.0f, 1.0f + __expf(-x));
}
__device__ __forceinline__ float ftanh(float x) {
    return 1.0f - __fdividef(2.0f, __expf(2.0f * x) + 1.0f);
}
__device__ __forceinline__ void cpa16(uint32_t s, const void* g) {
    asm volatile("cp.async.cg.shared.global [%0], [%1], 16;" :: "r"(s), "l"(g));
}
__device__ __forceinline__ void cpa_commit() {
    asm volatile("cp.async.commit_group;");
}

// ===========================================================================
// K1: xg[d][t][row][b] = W_ih x_t + b_ih + b_hh.  grid (8,512,2) x 256 thr.
// ===========================================================================
__global__ void k_xg(const int* __restrict__ ids, const float* __restrict__ emb,
                     const float* __restrict__ wif, const float* __restrict__ bif,
                     const float* __restrict__ bhf,
                     const float* __restrict__ wib, const float* __restrict__ bib,
                     const float* __restrict__ bhb)
{
    __shared__ float A_s[32][64];     // k-chunk x batch (8 KB)
    __shared__ ull   W_s[128][34];    // dup {w,w} pairs, 16B-aligned rows (34 KB)

    const int d  = blockIdx.z;
    const int t  = blockIdx.y;
    const int R  = blockIdx.x * 128;
    const int tid = threadIdx.x;

    if (blockIdx.x == 0 && t == 0 && d == 0 && tid < 8) g_ctr[tid][0] = 0;

    const int tp = (d == 0) ? t : (T_LEN - 1 - t);
    const float* w_ih = d ? wib : wif;
    const float* bi   = d ? bib : bif;
    const float* bh   = d ? bhb : bhf;

    const int rg = tid >> 3, bg = tid & 7;
    const int r0 = rg * 4,  b0 = bg * 8;

    const int lb  = tid & 63;
    const int seg = tid >> 6;
    const float* erow = emb + (size_t)ids[lb * T_LEN + tp] * EMBD;
    const int lr = tid >> 1, lh = tid & 1;

    ull acc[4][4];
#pragma unroll
    for (int rr = 0; rr < 4; rr++) {
        float bs = bi[R + r0 + rr] + bh[R + r0 + rr];
        ull p = pack2(bs, bs);
#pragma unroll
        for (int q = 0; q < 4; q++) acc[rr][q] = p;
    }

    for (int cc = 0; cc < 8; cc++) {
        __syncthreads();
        {   // A gather: 8 floats / thread
            float4 v0 = *(const float4*)(erow + cc * 32 + seg * 8);
            float4 v1 = *(const float4*)(erow + cc * 32 + seg * 8 + 4);
            int k = seg * 8;
            A_s[k+0][lb] = v0.x; A_s[k+1][lb] = v0.y; A_s[k+2][lb] = v0.z; A_s[k+3][lb] = v0.w;
            A_s[k+4][lb] = v1.x; A_s[k+5][lb] = v1.y; A_s[k+6][lb] = v1.z; A_s[k+7][lb] = v1.w;
        }
        {   // W chunk: 16 floats / thread, duplicated pairs
            const float4* w4 = (const float4*)(w_ih + (size_t)(R + lr) * EMBD + cc * 32 + lh * 16);
#pragma unroll
            for (int j = 0; j < 4; j++) {
                float4 v = w4[j];
                int k = lh * 16 + j * 4;
                W_s[lr][k+0] = pack2(v.x, v.x);
                W_s[lr][k+1] = pack2(v.y, v.y);
                W_s[lr][k+2] = pack2(v.z, v.z);
                W_s[lr][k+3] = pack2(v.w, v.w);
            }
        }
        __syncthreads();
#pragma unroll
        for (int kk = 0; kk < 32; kk += 2) {
            ulonglong2 wv[4];
#pragma unroll
            for (int rr = 0; rr < 4; rr++)
                wv[rr] = *(const ulonglong2*)&W_s[r0 + rr][kk];
            ulonglong2 aA0 = *(const ulonglong2*)&A_s[kk][b0];
            ulonglong2 aB0 = *(const ulonglong2*)&A_s[kk][b0 + 4];
            ulonglong2 aA1 = *(const ulonglong2*)&A_s[kk + 1][b0];
            ulonglong2 aB1 = *(const ulonglong2*)&A_s[kk + 1][b0 + 4];
#pragma unroll
            for (int rr = 0; rr < 4; rr++) {
                acc[rr][0] = fma2(wv[rr].x, aA0.x, acc[rr][0]);
                acc[rr][1] = fma2(wv[rr].x, aA0.y, acc[rr][1]);
                acc[rr][2] = fma2(wv[rr].x, aB0.x, acc[rr][2]);
                acc[rr][3] = fma2(wv[rr].x, aB0.y, acc[rr][3]);
                acc[rr][0] = fma2(wv[rr].y, aA1.x, acc[rr][0]);
                acc[rr][1] = fma2(wv[rr].y, aA1.y, acc[rr][1]);
                acc[rr][2] = fma2(wv[rr].y, aB1.x, acc[rr][2]);
                acc[rr][3] = fma2(wv[rr].y, aB1.y, acc[rr][3]);
            }
        }
    }
#pragma unroll
    for (int rr = 0; rr < 4; rr++) {
        ull* op = (ull*)&g_xg[d][t][R + r0 + rr][b0];
        op[0] = acc[rr][0]; op[1] = acc[rr][1]; op[2] = acc[rr][2]; op[3] = acc[rr][3];
    }
}

// ===========================================================================
// K2: recurrence. 128 persistent CTAs x 128 thr. CTA=(dir, 4 hidden units).
// Sync: monotone split arrival counters (4/dir); consumers poll >= 16*t.
// ===========================================================================
__global__ void __launch_bounds__(128, 1)
k_lstm(const float* __restrict__ whhf, const float* __restrict__ whhb)
{
    extern __shared__ ull smu[];
    ull* W2  = smu;          // [16][256] dup pairs (32 KB)
    ull* h_u = smu + 4096;   // [256][32] h pairs   (64 KB)

    const int cta = blockIdx.x;
    const int d = cta >> 6, s = cta & 63;
    const int tid = threadIdx.x;
    const int w = tid >> 5, l = tid & 31;
    const int u = (s << 2) + w;
    const float* whh = d ? whhb : whhf;

    for (int e = tid; e < 16 * 256; e += 128) {
        int r = e >> 8, k = e & 255;
        float v = whh[(size_t)((r >> 2) * 256 + (s << 2) + (r & 3)) * 256 + k];
        W2[e] = pack2(v, v);
    }
    const ulonglong2* wv0 = (const ulonglong2*)(W2 + ((0 * 4 + w) << 8));
    const ulonglong2* wv1 = (const ulonglong2*)(W2 + ((1 * 4 + w) << 8));
    const ulonglong2* wv2 = (const ulonglong2*)(W2 + ((2 * 4 + w) << 8));
    const ulonglong2* wv3 = (const ulonglong2*)(W2 + ((3 * 4 + w) << 8));
    const ull* hl = h_u + l;
    uint32_t hdst0 = (uint32_t)__cvta_generic_to_shared(h_u) + tid * 16;

    float c0 = 0.f, c1 = 0.f;
    __syncthreads();

    for (int t = 0; t < T_LEN; t++) {
        ull a0 = *(const ull*)&g_xg[d][t][      u][l * 2];
        ull a1 = *(const ull*)&g_xg[d][t][256 + u][l * 2];
        ull a2 = *(const ull*)&g_xg[d][t][512 + u][l * 2];
        ull a3 = *(const ull*)&g_xg[d][t][768 + u][l * 2];

        if (t > 0) {
            if (tid == 0) {
                unsigned need = (unsigned)(t << 4);
                while (*(volatile unsigned*)&g_ctr[4*d+0][0] < need ||
                       *(volatile unsigned*)&g_ctr[4*d+1][0] < need ||
                       *(volatile unsigned*)&g_ctr[4*d+2][0] < need ||
                       *(volatile unsigned*)&g_ctr[4*d+3][0] < need) {
                    __nanosleep(32);
                }
                __threadfence();
            }
            __syncthreads();

            const char* src = (const char*)&g_h[d][t - 1][0][0] + tid * 16;
            uint32_t dst = hdst0;
#pragma unroll
            for (int i = 0; i < 16; i++) { cpa16(dst, src); dst += 2048; src += 2048; }
            cpa_commit();
#pragma unroll
            for (int i = 0; i < 16; i++) { cpa16(dst, src); dst += 2048; src += 2048; }
            cpa_commit();

            asm volatile("cp.async.wait_group 1;");
            __syncthreads();
#pragma unroll 8
            for (int k = 0; k < 128; k += 2) {
                ull hp0 = hl[k << 5], hp1 = hl[(k + 1) << 5];
                ulonglong2 q0 = wv0[k >> 1], q1 = wv1[k >> 1];
                ulonglong2 q2 = wv2[k >> 1], q3 = wv3[k >> 1];
                a0 = fma2(q0.x, hp0, a0); a0 = fma2(q0.y, hp1, a0);
                a1 = fma2(q1.x, hp0, a1); a1 = fma2(q1.y, hp1, a1);
                a2 = fma2(q2.x, hp0, a2); a2 = fma2(q2.y, hp1, a2);
                a3 = fma2(q3.x, hp0, a3); a3 = fma2(q3.y, hp1, a3);
            }
            asm volatile("cp.async.wait_group 0;");
            __syncthreads();
#pragma unroll 8
            for (int k = 128; k < 256; k += 2) {
                ull hp0 = hl[k << 5], hp1 = hl[(k + 1) << 5];
                ulonglong2 q0 = wv0[k >> 1], q1 = wv1[k >> 1];
                ulonglong2 q2 = wv2[k >> 1], q3 = wv3[k >> 1];
                a0 = fma2(q0.x, hp0, a0); a0 = fma2(q0.y, hp1, a0);
                a1 = fma2(q1.x, hp0, a1); a1 = fma2(q1.y, hp1, a1);
                a2 = fma2(q2.x, hp0, a2); a2 = fma2(q2.y, hp1, a2);
                a3 = fma2(q3.x, hp0, a3); a3 = fma2(q3.y, hp1, a3);
            }
        }

        float i0,i1,f0,f1,gg0,gg1,o0,o1;
        unpack2(a0,i0,i1); unpack2(a1,f0,f1); unpack2(a2,gg0,gg1); unpack2(a3,o0,o1);
        c0 = fsig(f0)*c0 + fsig(i0)*ftanh(gg0);
        c1 = fsig(f1)*c1 + fsig(i1)*ftanh(gg1);
        float h0 = fsig(o0)*ftanh(c0);
        float h1 = fsig(o1)*ftanh(c1);
        *(ull*)&g_h[d][t][u][l * 2] = pack2(h0, h1);

        __threadfence();
        __syncthreads();
        if (tid == 0) atomicAdd(&g_ctr[4*d + (s & 3)][0], 1u);
    }
}

// ===========================================================================
// K3: emissions.  grid T_LEN x 256 thr; thread = (b, u-quarter).
// ===========================================================================
__global__ void k_emis(const float* __restrict__ w_cls, const float* __restrict__ b_cls)
{
    __shared__ float wc[512][12];      // wc[u][l]
    __shared__ float red[4][64][10];
    const int tid = threadIdx.x, t = blockIdx.x;

    for (int i = tid; i < LL * 512; i += 256) wc[i & 511][i >> 9] = w_cls[i];
    __syncthreads();

    const int b = tid & 63, qa = tid >> 6;
    const float* hp = (qa < 2) ? &g_h[0][t][qa * 128][0]
                               : &g_h[1][T_LEN - 1 - t][(qa - 2) * 128][0];
    float acc[LL];
#pragma unroll
    for (int ll = 0; ll < LL; ll++) acc[ll] = 0.f;
    for (int uu = 0; uu < 128; uu++) {
        float hv = hp[(uu << 6) + b];
        const float* wr = &wc[qa * 128 + uu][0];
#pragma unroll
        for (int ll = 0; ll < LL; ll++) acc[ll] += hv * wr[ll];
    }
#pragma unroll
    for (int ll = 0; ll < LL; ll++) red[qa][b][ll] = acc[ll];
    __syncthreads();
    if (tid < 64) {
#pragma unroll
        for (int ll = 0; ll < LL; ll++)
            g_em[tid][t][ll] = red[0][tid][ll] + red[1][tid][ll]
                             + red[2][tid][ll] + red[3][tid][ll] + b_cls[ll];
    }
}

// ===========================================================================
// K4: CRF numerator + forward per batch (one warp / batch).
// ===========================================================================
__global__ void k_crf(const int* __restrict__ labels, const int* __restrict__ mask,
                      const float* __restrict__ trans, const float* __restrict__ start,
                      const float* __restrict__ endv)
{
    const int warp = threadIdx.x >> 5, lane = threadIdx.x & 31;
    const int b = blockIdx.x * 8 + warp;
    if (b >= BB) return;
    const float NEG = -1e30f;
    const int* lab = labels + b * T_LEN;
    const int* msk = mask   + b * T_LEN;
    const float* em = &g_em[b][0][0];

    float numl = 0.f; int msum = 0;
    for (int t = lane; t < T_LEN; t += 32) msum += msk[t];
    for (int t = 1 + lane; t < T_LEN; t += 32) {
        float mf = (float)msk[t];
        numl += mf * (trans[lab[t - 1] * LL + lab[t]] + em[t * LL + lab[t]]);
    }
#pragma unroll
    for (int o = 16; o; o >>= 1) {
        numl += __shfl_xor_sync(0xFFFFFFFFu, numl, o);
        msum += __shfl_xor_sync(0xFFFFFFFFu, msum, o);
    }

    float trc[LL];
#pragma unroll
    for (int i = 0; i < LL; i++) trc[i] = (lane < LL) ? trans[i * LL + lane] : 0.f;
    float alpha = (lane < LL) ? start[lane] + em[lane] : NEG;

    for (int t = 1; t < T_LEN; t++) {
        float emj = (lane < LL) ? em[t * LL + lane] : 0.f;  // prefetched early
        int   mt  = msk[t];
        float tv[LL], m = NEG;
#pragma unroll
        for (int i = 0; i < LL; i++) {
            float ai = __shfl_sync(0xFFFFFFFFu, alpha, i);
            tv[i] = ai + trc[i];
            m = fmaxf(m, tv[i]);
        }
        float ss = 0.f;
#pragma unroll
        for (int i = 0; i < LL; i++) ss += __expf(tv[i] - m);
        float nxt = m + __logf(ss) + emj;
        if (lane < LL && mt) alpha = nxt;
    }

    float v = (lane < LL) ? alpha + endv[lane] : NEG;
    float m = v;
#pragma unroll
    for (int o = 16; o; o >>= 1) m = fmaxf(m, __shfl_xor_sync(0xFFFFFFFFu, m, o));
    float sv = __expf(v - m);
#pragma unroll
    for (int o = 16; o; o >>= 1) sv += __shfl_xor_sync(0xFFFFFFFFu, sv, o);
    float logZ = m + __logf(sv);

    if (lane == 0) {
        float num = numl + start[lab[0]] + em[lab[0]] + endv[lab[msum - 1]];
        g_res[b] = num - logZ;
    }
}

__global__ void k_final(float* out)
{
    const int tid = threadIdx.x;
    float v = g_res[tid];
#pragma unroll
    for (int o = 16; o; o >>= 1) v += __shfl_xor_sync(0xFFFFFFFFu, v, o);
    __shared__ float sred[2];
    if ((tid & 31) == 0) sred[tid >> 5] = v;
    __syncthreads();
    if (tid == 0) out[0] = -(sred[0] + sred[1]) / 64.0f;
}

// ===========================================================================
extern "C" void kernel_launch(void* const* d_in, const int* in_sizes, int n_in,
                              void* d_out, int out_size)
{
    const int*   ids   = (const int*)  d_in[0];
    const int*   msk   = (const int*)  d_in[1];
    const int*   lab   = (const int*)  d_in[2];
    const float* emb   = (const float*)d_in[3];
    const float* wif   = (const float*)d_in[4];
    const float* whf   = (const float*)d_in[5];
    const float* bif   = (const float*)d_in[6];
    const float* bhf   = (const float*)d_in[7];
    const float* wib   = (const float*)d_in[8];
    const float* whb   = (const float*)d_in[9];
    const float* bib   = (const float*)d_in[10];
    const float* bhb   = (const float*)d_in[11];
    const float* wcls  = (const float*)d_in[12];
    const float* bcls  = (const float*)d_in[13];
    const float* trans = (const float*)d_in[14];
    const float* start = (const float*)d_in[15];
    const float* endv  = (const float*)d_in[16];

    cudaFuncSetAttribute(k_lstm, cudaFuncAttributeMaxDynamicSharedMemorySize, 98304);

    k_xg  <<<dim3(8, T_LEN, 2), 256>>>(ids, emb, wif, bif, bhf, wib, bib, bhb);
    k_lstm<<<NCTA, 128, 98304>>>(whf, whb);
    k_emis<<<T_LEN, 256>>>(wcls, bcls);
    k_crf <<<8, 256>>>(lab, msk, trans, start, endv);
    k_final<<<1, 64>>>((float*)d_out);
}

// round 4
// speedup vs baseline: 2.2246x; 1.1806x over previous
#include <cuda_runtime.h>
#include <cuda_bf16.h>
#include <cstdint>

#define T_LEN 512
#define BB    64
#define EMBD  256
#define HD    256
#define G4    1024
#define LL    9
#define NCTA  128

typedef unsigned long long ull;

// ------------------------- device scratch ----------------------------------
__device__ float g_xg[2][T_LEN][G4][BB];   // pre-activations, b fastest
__device__ float g_h [2][T_LEN][HD][BB];   // hidden states
__device__ float g_em[BB][T_LEN][LL];
__device__ float g_res[BB];
__device__ unsigned g_ctr[8][32];          // [dir*4+grp][pad] arrival counters

// ------------------------- helpers -----------------------------------------
__device__ __forceinline__ ull pack2(float a, float b) {
    ull r; asm("mov.b64 %0, {%1,%2};" : "=l"(r) : "f"(a), "f"(b)); return r;
}
__device__ __forceinline__ void unpack2(ull v, float& a, float& b) {
    asm("mov.b64 {%0,%1}, %2;" : "=f"(a), "=f"(b) : "l"(v));
}
__device__ __forceinline__ ull fma2(ull a, ull b, ull c) {
    ull d; asm("fma.rn.f32x2 %0, %1, %2, %3;" : "=l"(d) : "l"(a), "l"(b), "l"(c));
    return d;
}
__device__ __forceinline__ float fsig(float x) {
    return __fdividef(1.0f, 1.0f + __expf(-x));
}
__device__ __forceinline__ float ftanh(float x) {
    return 1.0f - __fdividef(2.0f, __expf(2.0f * x) + 1.0f);
}
__device__ __forceinline__ void cpa16(uint32_t s, const void* g) {
    asm volatile("cp.async.cg.shared.global [%0], [%1], 16;" :: "r"(s), "l"(g));
}
__device__ __forceinline__ void cpa_commit() {
    asm volatile("cp.async.commit_group;");
}
__device__ __forceinline__ unsigned ld_acq(const unsigned* p) {
    unsigned v;
    asm volatile("ld.acquire.gpu.global.u32 %0, [%1];" : "=r"(v) : "l"(p) : "memory");
    return v;
}
__device__ __forceinline__ void red_rel(unsigned* p, unsigned v) {
    asm volatile("red.release.gpu.global.add.u32 [%0], %1;" :: "l"(p), "r"(v) : "memory");
}

// ===========================================================================
// K1: xg[d][t][row][b] = W_ih x_t + b_ih + b_hh.  grid (8,512,2) x 256 thr.
// ===========================================================================
__global__ void k_xg(const int* __restrict__ ids, const float* __restrict__ emb,
                     const float* __restrict__ wif, const float* __restrict__ bif,
                     const float* __restrict__ bhf,
                     const float* __restrict__ wib, const float* __restrict__ bib,
                     const float* __restrict__ bhb)
{
    __shared__ float A_s[32][64];     // k-chunk x batch (8 KB)
    __shared__ ull   W_s[128][34];    // dup {w,w} pairs, 16B-aligned rows (34 KB)

    const int d  = blockIdx.z;
    const int t  = blockIdx.y;
    const int R  = blockIdx.x * 128;
    const int tid = threadIdx.x;

    if (blockIdx.x == 0 && t == 0 && d == 0 && tid < 8) g_ctr[tid][0] = 0;

    const int tp = (d == 0) ? t : (T_LEN - 1 - t);
    const float* w_ih = d ? wib : wif;
    const float* bi   = d ? bib : bif;
    const float* bh   = d ? bhb : bhf;

    const int rg = tid >> 3, bg = tid & 7;
    const int r0 = rg * 4,  b0 = bg * 8;

    const int lb  = tid & 63;
    const int seg = tid >> 6;
    const float* erow = emb + (size_t)ids[lb * T_LEN + tp] * EMBD;
    const int lr = tid >> 1, lh = tid & 1;

    ull acc[4][4];
#pragma unroll
    for (int rr = 0; rr < 4; rr++) {
        float bs = bi[R + r0 + rr] + bh[R + r0 + rr];
        ull p = pack2(bs, bs);
#pragma unroll
        for (int q = 0; q < 4; q++) acc[rr][q] = p;
    }

    for (int cc = 0; cc < 8; cc++) {
        __syncthreads();
        {   // A gather: 8 floats / thread
            float4 v0 = *(const float4*)(erow + cc * 32 + seg * 8);
            float4 v1 = *(const float4*)(erow + cc * 32 + seg * 8 + 4);
            int k = seg * 8;
            A_s[k+0][lb] = v0.x; A_s[k+1][lb] = v0.y; A_s[k+2][lb] = v0.z; A_s[k+3][lb] = v0.w;
            A_s[k+4][lb] = v1.x; A_s[k+5][lb] = v1.y; A_s[k+6][lb] = v1.z; A_s[k+7][lb] = v1.w;
        }
        {   // W chunk: 16 floats / thread, duplicated pairs
            const float4* w4 = (const float4*)(w_ih + (size_t)(R + lr) * EMBD + cc * 32 + lh * 16);
#pragma unroll
            for (int j = 0; j < 4; j++) {
                float4 v = w4[j];
                int k = lh * 16 + j * 4;
                W_s[lr][k+0] = pack2(v.x, v.x);
                W_s[lr][k+1] = pack2(v.y, v.y);
                W_s[lr][k+2] = pack2(v.z, v.z);
                W_s[lr][k+3] = pack2(v.w, v.w);
            }
        }
        __syncthreads();
#pragma unroll
        for (int kk = 0; kk < 32; kk += 2) {
            ulonglong2 wv[4];
#pragma unroll
            for (int rr = 0; rr < 4; rr++)
                wv[rr] = *(const ulonglong2*)&W_s[r0 + rr][kk];
            ulonglong2 aA0 = *(const ulonglong2*)&A_s[kk][b0];
            ulonglong2 aB0 = *(const ulonglong2*)&A_s[kk][b0 + 4];
            ulonglong2 aA1 = *(const ulonglong2*)&A_s[kk + 1][b0];
            ulonglong2 aB1 = *(const ulonglong2*)&A_s[kk + 1][b0 + 4];
#pragma unroll
            for (int rr = 0; rr < 4; rr++) {
                acc[rr][0] = fma2(wv[rr].x, aA0.x, acc[rr][0]);
                acc[rr][1] = fma2(wv[rr].x, aA0.y, acc[rr][1]);
                acc[rr][2] = fma2(wv[rr].x, aB0.x, acc[rr][2]);
                acc[rr][3] = fma2(wv[rr].x, aB0.y, acc[rr][3]);
                acc[rr][0] = fma2(wv[rr].y, aA1.x, acc[rr][0]);
                acc[rr][1] = fma2(wv[rr].y, aA1.y, acc[rr][1]);
                acc[rr][2] = fma2(wv[rr].y, aB1.x, acc[rr][2]);
                acc[rr][3] = fma2(wv[rr].y, aB1.y, acc[rr][3]);
            }
        }
    }
#pragma unroll
    for (int rr = 0; rr < 4; rr++) {
        ull* op = (ull*)&g_xg[d][t][R + r0 + rr][b0];
        op[0] = acc[rr][0]; op[1] = acc[rr][1]; op[2] = acc[rr][2]; op[3] = acc[rr][3];
    }
}

// ===========================================================================
// K2: recurrence. 128 persistent CTAs x 128 thr. CTA=(dir, 4 hidden units).
// Sync: monotone split counters, release atomics / acquire polls, no fences.
// ===========================================================================
__global__ void __launch_bounds__(128, 1)
k_lstm(const float* __restrict__ whhf, const float* __restrict__ whhb)
{
    extern __shared__ ull smu[];
    ull* W2  = smu;          // [16][256] dup pairs (32 KB)
    ull* h_u = smu + 4096;   // [256][32] h pairs   (64 KB)

    const int cta = blockIdx.x;
    const int d = cta >> 6, s = cta & 63;
    const int tid = threadIdx.x;
    const int w = tid >> 5, l = tid & 31;
    const int u = (s << 2) + w;
    const float* whh = d ? whhb : whhf;

    for (int e = tid; e < 16 * 256; e += 128) {
        int r = e >> 8, k = e & 255;
        float v = whh[(size_t)((r >> 2) * 256 + (s << 2) + (r & 3)) * 256 + k];
        W2[e] = pack2(v, v);
    }
    const ulonglong2* wv0 = (const ulonglong2*)(W2 + ((0 * 4 + w) << 8));
    const ulonglong2* wv1 = (const ulonglong2*)(W2 + ((1 * 4 + w) << 8));
    const ulonglong2* wv2 = (const ulonglong2*)(W2 + ((2 * 4 + w) << 8));
    const ulonglong2* wv3 = (const ulonglong2*)(W2 + ((3 * 4 + w) << 8));
    const ull* hl = h_u + l;
    uint32_t hdst0 = (uint32_t)__cvta_generic_to_shared(h_u) + tid * 16;
    unsigned* my_ctr = &g_ctr[4 * d + (s & 3)][0];
    const unsigned* poll_ctr = &g_ctr[4 * d + tid][0];   // valid for tid<4

    float c0 = 0.f, c1 = 0.f;
    __syncthreads();

    for (int t = 0; t < T_LEN; t++) {
        ull a0 = *(const ull*)&g_xg[d][t][      u][l * 2];
        ull a1 = *(const ull*)&g_xg[d][t][256 + u][l * 2];
        ull a2 = *(const ull*)&g_xg[d][t][512 + u][l * 2];
        ull a3 = *(const ull*)&g_xg[d][t][768 + u][l * 2];

        if (t > 0) {
            if (tid < 4) {
                const unsigned need = (unsigned)(t << 4);
                while (ld_acq(poll_ctr) < need) { }
            }
            __syncthreads();

            const char* src = (const char*)&g_h[d][t - 1][0][0] + tid * 16;
            uint32_t dst = hdst0;
#pragma unroll
            for (int i = 0; i < 16; i++) { cpa16(dst, src); dst += 2048; src += 2048; }
            cpa_commit();
#pragma unroll
            for (int i = 0; i < 16; i++) { cpa16(dst, src); dst += 2048; src += 2048; }
            cpa_commit();

            asm volatile("cp.async.wait_group 1;");
            __syncthreads();
#pragma unroll 8
            for (int k = 0; k < 128; k += 2) {
                ull hp0 = hl[k << 5], hp1 = hl[(k + 1) << 5];
                ulonglong2 q0 = wv0[k >> 1], q1 = wv1[k >> 1];
                ulonglong2 q2 = wv2[k >> 1], q3 = wv3[k >> 1];
                a0 = fma2(q0.x, hp0, a0); a0 = fma2(q0.y, hp1, a0);
                a1 = fma2(q1.x, hp0, a1); a1 = fma2(q1.y, hp1, a1);
                a2 = fma2(q2.x, hp0, a2); a2 = fma2(q2.y, hp1, a2);
                a3 = fma2(q3.x, hp0, a3); a3 = fma2(q3.y, hp1, a3);
            }
            asm volatile("cp.async.wait_group 0;");
            __syncthreads();
#pragma unroll 8
            for (int k = 128; k < 256; k += 2) {
                ull hp0 = hl[k << 5], hp1 = hl[(k + 1) << 5];
                ulonglong2 q0 = wv0[k >> 1], q1 = wv1[k >> 1];
                ulonglong2 q2 = wv2[k >> 1], q3 = wv3[k >> 1];
                a0 = fma2(q0.x, hp0, a0); a0 = fma2(q0.y, hp1, a0);
                a1 = fma2(q1.x, hp0, a1); a1 = fma2(q1.y, hp1, a1);
                a2 = fma2(q2.x, hp0, a2); a2 = fma2(q2.y, hp1, a2);
                a3 = fma2(q3.x, hp0, a3); a3 = fma2(q3.y, hp1, a3);
            }
        }

        float i0,i1,f0,f1,gg0,gg1,o0,o1;
        unpack2(a0,i0,i1); unpack2(a1,f0,f1); unpack2(a2,gg0,gg1); unpack2(a3,o0,o1);
        c0 = fsig(f0)*c0 + fsig(i0)*ftanh(gg0);
        c1 = fsig(f1)*c1 + fsig(i1)*ftanh(gg1);
        float h0 = fsig(o0)*ftanh(c0);
        float h1 = fsig(o1)*ftanh(c1);
        *(ull*)&g_h[d][t][u][l * 2] = pack2(h0, h1);

        __syncthreads();
        if (tid == 0) red_rel(my_ctr, 1u);
    }
}

// ===========================================================================
// K3: emissions.  grid T_LEN x 256 thr; thread = (b, u-quarter).
// ===========================================================================
__global__ void k_emis(const float* __restrict__ w_cls, const float* __restrict__ b_cls)
{
    __shared__ float wc[512][12];      // wc[u][l]
    __shared__ float red[4][64][10];
    const int tid = threadIdx.x, t = blockIdx.x;

    for (int i = tid; i < LL * 512; i += 256) wc[i & 511][i >> 9] = w_cls[i];
    __syncthreads();

    const int b = tid & 63, qa = tid >> 6;
    const float* hp = (qa < 2) ? &g_h[0][t][qa * 128][0]
                               : &g_h[1][T_LEN - 1 - t][(qa - 2) * 128][0];
    float acc[LL];
#pragma unroll
    for (int ll = 0; ll < LL; ll++) acc[ll] = 0.f;
    for (int uu = 0; uu < 128; uu++) {
        float hv = hp[(uu << 6) + b];
        const float* wr = &wc[qa * 128 + uu][0];
#pragma unroll
        for (int ll = 0; ll < LL; ll++) acc[ll] += hv * wr[ll];
    }
#pragma unroll
    for (int ll = 0; ll < LL; ll++) red[qa][b][ll] = acc[ll];
    __syncthreads();
    if (tid < 64) {
#pragma unroll
        for (int ll = 0; ll < LL; ll++)
            g_em[tid][t][ll] = red[0][tid][ll] + red[1][tid][ll]
                             + red[2][tid][ll] + red[3][tid][ll] + b_cls[ll];
    }
}

// ===========================================================================
// K4: CRF numerator + forward per batch (one warp / batch).
// ===========================================================================
__global__ void k_crf(const int* __restrict__ labels, const int* __restrict__ mask,
                      const float* __restrict__ trans, const float* __restrict__ start,
                      const float* __restrict__ endv)
{
    const int warp = threadIdx.x >> 5, lane = threadIdx.x & 31;
    const int b = blockIdx.x * 8 + warp;
    if (b >= BB) return;
    const float NEG = -1e30f;
    const int* lab = labels + b * T_LEN;
    const int* msk = mask   + b * T_LEN;
    const float* em = &g_em[b][0][0];

    float numl = 0.f; int msum = 0;
    for (int t = lane; t < T_LEN; t += 32) msum += msk[t];
    for (int t = 1 + lane; t < T_LEN; t += 32) {
        float mf = (float)msk[t];
        numl += mf * (trans[lab[t - 1] * LL + lab[t]] + em[t * LL + lab[t]]);
    }
#pragma unroll
    for (int o = 16; o; o >>= 1) {
        numl += __shfl_xor_sync(0xFFFFFFFFu, numl, o);
        msum += __shfl_xor_sync(0xFFFFFFFFu, msum, o);
    }

    float trc[LL];
#pragma unroll
    for (int i = 0; i < LL; i++) trc[i] = (lane < LL) ? trans[i * LL + lane] : 0.f;
    float alpha = (lane < LL) ? start[lane] + em[lane] : NEG;

    for (int t = 1; t < T_LEN; t++) {
        float emj = (lane < LL) ? em[t * LL + lane] : 0.f;
        int   mt  = msk[t];
        float tv[LL], m = NEG;
#pragma unroll
        for (int i = 0; i < LL; i++) {
            float ai = __shfl_sync(0xFFFFFFFFu, alpha, i);
            tv[i] = ai + trc[i];
            m = fmaxf(m, tv[i]);
        }
        float ss = 0.f;
#pragma unroll
        for (int i = 0; i < LL; i++) ss += __expf(tv[i] - m);
        float nxt = m + __logf(ss) + emj;
        if (lane < LL && mt) alpha = nxt;
    }

    float v = (lane < LL) ? alpha + endv[lane] : NEG;
    float m = v;
#pragma unroll
    for (int o = 16; o; o >>= 1) m = fmaxf(m, __shfl_xor_sync(0xFFFFFFFFu, m, o));
    float sv = __expf(v - m);
#pragma unroll
    for (int o = 16; o; o >>= 1) sv += __shfl_xor_sync(0xFFFFFFFFu, sv, o);
    float logZ = m + __logf(sv);

    if (lane == 0) {
        float num = numl + start[lab[0]] + em[lab[0]] + endv[lab[msum - 1]];
        g_res[b] = num - logZ;
    }
}

__global__ void k_final(float* out)
{
    const int tid = threadIdx.x;
    float v = g_res[tid];
#pragma unroll
    for (int o = 16; o; o >>= 1) v += __shfl_xor_sync(0xFFFFFFFFu, v, o);
    __shared__ float sred[2];
    if ((tid & 31) == 0) sred[tid >> 5] = v;
    __syncthreads();
    if (tid == 0) out[0] = -(sred[0] + sred[1]) / 64.0f;
}

// ===========================================================================
extern "C" void kernel_launch(void* const* d_in, const int* in_sizes, int n_in,
                              void* d_out, int out_size)
{
    const int*   ids   = (const int*)  d_in[0];
    const int*   msk   = (const int*)  d_in[1];
    const int*   lab   = (const int*)  d_in[2];
    const float* emb   = (const float*)d_in[3];
    const float* wif   = (const float*)d_in[4];
    const float* whf   = (const float*)d_in[5];
    const float* bif   = (const float*)d_in[6];
    const float* bhf   = (const float*)d_in[7];
    const float* wib   = (const float*)d_in[8];
    const float* whb   = (const float*)d_in[9];
    const float* bib   = (const float*)d_in[10];
    const float* bhb   = (const float*)d_in[11];
    const float* wcls  = (const float*)d_in[12];
    const float* bcls  = (const float*)d_in[13];
    const float* trans = (const float*)d_in[14];
    const float* start = (const float*)d_in[15];
    const float* endv  = (const float*)d_in[16];

    cudaFuncSetAttribute(k_lstm, cudaFuncAttributeMaxDynamicSharedMemorySize, 98304);

    k_xg  <<<dim3(8, T_LEN, 2), 256>>>(ids, emb, wif, bif, bhf, wib, bib, bhb);
    k_lstm<<<NCTA, 128, 98304>>>(whf, whb);
    k_emis<<<T_LEN, 256>>>(wcls, bcls);
    k_crf <<<8, 256>>>(lab, msk, trans, start, endv);
    k_final<<<1, 64>>>((float*)d_out);
}

// round 5
// speedup vs baseline: 2.3289x; 1.0469x over previous
#include <cuda_runtime.h>
#include <cuda_bf16.h>
#include <cstdint>

#define T_LEN 512
#define BB    64
#define EMBD  256
#define HD    256
#define G4    1024
#define LL    9
#define NCTA  128

typedef unsigned long long ull;

// ------------------------- device scratch ----------------------------------
__device__ float g_xg[2][T_LEN][G4][BB];   // pre-activations, b fastest
__device__ float g_h [2][T_LEN][HD][BB];   // hidden states
__device__ float g_em[BB][T_LEN][LL];
__device__ float g_res[BB];
__device__ unsigned g_ctr[8][32];          // [dir*2+half][pad] arrival counters

// ------------------------- helpers -----------------------------------------
__device__ __forceinline__ ull pack2(float a, float b) {
    ull r; asm("mov.b64 %0, {%1,%2};" : "=l"(r) : "f"(a), "f"(b)); return r;
}
__device__ __forceinline__ void unpack2(ull v, float& a, float& b) {
    asm("mov.b64 {%0,%1}, %2;" : "=f"(a), "=f"(b) : "l"(v));
}
__device__ __forceinline__ ull fma2(ull a, ull b, ull c) {
    ull d; asm("fma.rn.f32x2 %0, %1, %2, %3;" : "=l"(d) : "l"(a), "l"(b), "l"(c));
    return d;
}
__device__ __forceinline__ ull add2(ull a, ull b) {
    ull d; asm("add.rn.f32x2 %0, %1, %2;" : "=l"(d) : "l"(a), "l"(b));
    return d;
}
__device__ __forceinline__ float fsig(float x) {
    return __fdividef(1.0f, 1.0f + __expf(-x));
}
__device__ __forceinline__ float ftanh(float x) {
    return 1.0f - __fdividef(2.0f, __expf(2.0f * x) + 1.0f);
}
__device__ __forceinline__ void cpa16(uint32_t s, const void* g) {
    asm volatile("cp.async.cg.shared.global [%0], [%1], 16;" :: "r"(s), "l"(g));
}
__device__ __forceinline__ void cpa_commit() {
    asm volatile("cp.async.commit_group;");
}
__device__ __forceinline__ unsigned ld_acq(const unsigned* p) {
    unsigned v;
    asm volatile("ld.acquire.gpu.global.u32 %0, [%1];" : "=r"(v) : "l"(p) : "memory");
    return v;
}
__device__ __forceinline__ void red_rel(unsigned* p, unsigned v) {
    asm volatile("red.release.gpu.global.add.u32 [%0], %1;" :: "l"(p), "r"(v) : "memory");
}
__device__ __forceinline__ void barn(int id) {
    asm volatile("bar.sync %0, 128;" :: "r"(id) : "memory");
}

// ===========================================================================
// K1: xg[d][t][row][b] = W_ih x_t + b_ih + b_hh.  grid (8,512,2) x 256 thr.
// ===========================================================================
__global__ void k_xg(const int* __restrict__ ids, const float* __restrict__ emb,
                     const float* __restrict__ wif, const float* __restrict__ bif,
                     const float* __restrict__ bhf,
                     const float* __restrict__ wib, const float* __restrict__ bib,
                     const float* __restrict__ bhb)
{
    __shared__ float A_s[32][64];
    __shared__ ull   W_s[128][34];

    const int d  = blockIdx.z;
    const int t  = blockIdx.y;
    const int R  = blockIdx.x * 128;
    const int tid = threadIdx.x;

    if (blockIdx.x == 0 && t == 0 && d == 0 && tid < 8) g_ctr[tid][0] = 0;

    const int tp = (d == 0) ? t : (T_LEN - 1 - t);
    const float* w_ih = d ? wib : wif;
    const float* bi   = d ? bib : bif;
    const float* bh   = d ? bhb : bhf;

    const int rg = tid >> 3, bg = tid & 7;
    const int r0 = rg * 4,  b0 = bg * 8;

    const int lb  = tid & 63;
    const int seg = tid >> 6;
    const float* erow = emb + (size_t)ids[lb * T_LEN + tp] * EMBD;
    const int lr = tid >> 1, lh = tid & 1;

    ull acc[4][4];
#pragma unroll
    for (int rr = 0; rr < 4; rr++) {
        float bs = bi[R + r0 + rr] + bh[R + r0 + rr];
        ull p = pack2(bs, bs);
#pragma unroll
        for (int q = 0; q < 4; q++) acc[rr][q] = p;
    }

    for (int cc = 0; cc < 8; cc++) {
        __syncthreads();
        {
            float4 v0 = *(const float4*)(erow + cc * 32 + seg * 8);
            float4 v1 = *(const float4*)(erow + cc * 32 + seg * 8 + 4);
            int k = seg * 8;
            A_s[k+0][lb] = v0.x; A_s[k+1][lb] = v0.y; A_s[k+2][lb] = v0.z; A_s[k+3][lb] = v0.w;
            A_s[k+4][lb] = v1.x; A_s[k+5][lb] = v1.y; A_s[k+6][lb] = v1.z; A_s[k+7][lb] = v1.w;
        }
        {
            const float4* w4 = (const float4*)(w_ih + (size_t)(R + lr) * EMBD + cc * 32 + lh * 16);
#pragma unroll
            for (int j = 0; j < 4; j++) {
                float4 v = w4[j];
                int k = lh * 16 + j * 4;
                W_s[lr][k+0] = pack2(v.x, v.x);
                W_s[lr][k+1] = pack2(v.y, v.y);
                W_s[lr][k+2] = pack2(v.z, v.z);
                W_s[lr][k+3] = pack2(v.w, v.w);
            }
        }
        __syncthreads();
#pragma unroll
        for (int kk = 0; kk < 32; kk += 2) {
            ulonglong2 wv[4];
#pragma unroll
            for (int rr = 0; rr < 4; rr++)
                wv[rr] = *(const ulonglong2*)&W_s[r0 + rr][kk];
            ulonglong2 aA0 = *(const ulonglong2*)&A_s[kk][b0];
            ulonglong2 aB0 = *(const ulonglong2*)&A_s[kk][b0 + 4];
            ulonglong2 aA1 = *(const ulonglong2*)&A_s[kk + 1][b0];
            ulonglong2 aB1 = *(const ulonglong2*)&A_s[kk + 1][b0 + 4];
#pragma unroll
            for (int rr = 0; rr < 4; rr++) {
                acc[rr][0] = fma2(wv[rr].x, aA0.x, acc[rr][0]);
                acc[rr][1] = fma2(wv[rr].x, aA0.y, acc[rr][1]);
                acc[rr][2] = fma2(wv[rr].x, aB0.x, acc[rr][2]);
                acc[rr][3] = fma2(wv[rr].x, aB0.y, acc[rr][3]);
                acc[rr][0] = fma2(wv[rr].y, aA1.x, acc[rr][0]);
                acc[rr][1] = fma2(wv[rr].y, aA1.y, acc[rr][1]);
                acc[rr][2] = fma2(wv[rr].y, aB1.x, acc[rr][2]);
                acc[rr][3] = fma2(wv[rr].y, aB1.y, acc[rr][3]);
            }
        }
    }
#pragma unroll
    for (int rr = 0; rr < 4; rr++) {
        ull* op = (ull*)&g_xg[d][t][R + r0 + rr][b0];
        op[0] = acc[rr][0]; op[1] = acc[rr][1]; op[2] = acc[rr][2]; op[3] = acc[rr][3];
    }
}

// ===========================================================================
// K2: recurrence. 128 persistent CTAs x 256 thr (8 warps, K-split halves).
//   wg0 (warps 0-3): k in [0,128)   — units 0-127  (CTAs s<32)
//   wg1 (warps 4-7): k in [128,256) — units 128-255 (CTAs s>=32)
// Each wg polls its half counter (>= 32*t), copies its 32 KB, GEMMs its half;
// wg1 partials merged into wg0 via smem, wg0 does activations + store + rel.
// ===========================================================================
__global__ void __launch_bounds__(256, 1)
k_lstm(const float* __restrict__ whhf, const float* __restrict__ whhb)
{
    extern __shared__ ull smu[];
    ull* W2  = smu;            // [16][256] dup pairs (32 KB)
    ull* h_u = smu + 4096;     // [256][32] h pairs   (64 KB)
    ull* red = smu + 12288;    // [4][128] partials   (4 KB)

    const int cta = blockIdx.x;
    const int d = cta >> 6, s = cta & 63;
    const int tid = threadIdx.x;
    const int hg   = tid >> 7;       // warp-group half (0/1)
    const int wtid = tid & 127;
    const int w = (tid >> 5) & 3, l = tid & 31;
    const int u = (s << 2) + w;
    const float* whh = d ? whhb : whhf;

    for (int e = tid; e < 16 * 256; e += 256) {
        int r = e >> 8, k = e & 255;
        float v = whh[(size_t)((r >> 2) * 256 + (s << 2) + (r & 3)) * 256 + k];
        W2[e] = pack2(v, v);
    }
    const int kb = hg << 7;    // k range base for this wg
    const ulonglong2* wv0 = (const ulonglong2*)(W2 + ((0 * 4 + w) << 8) + kb);
    const ulonglong2* wv1 = (const ulonglong2*)(W2 + ((1 * 4 + w) << 8) + kb);
    const ulonglong2* wv2 = (const ulonglong2*)(W2 + ((2 * 4 + w) << 8) + kb);
    const ulonglong2* wv3 = (const ulonglong2*)(W2 + ((3 * 4 + w) << 8) + kb);
    const ull* hl = h_u + (kb << 5) + l;
    uint32_t hdst0 = (uint32_t)__cvta_generic_to_shared(h_u) + hg * 32768 + wtid * 16;
    unsigned* my_ctr = &g_ctr[2 * d + (s >> 5)][0];
    const unsigned* poll_ctr = &g_ctr[2 * d + hg][0];

    float c0 = 0.f, c1 = 0.f;
    __syncthreads();

    for (int t = 0; t < T_LEN; t++) {
        ull a0 = 0, a1 = 0, a2 = 0, a3 = 0;
        if (hg == 0) {
            a0 = *(const ull*)&g_xg[d][t][      u][l * 2];
            a1 = *(const ull*)&g_xg[d][t][256 + u][l * 2];
            a2 = *(const ull*)&g_xg[d][t][512 + u][l * 2];
            a3 = *(const ull*)&g_xg[d][t][768 + u][l * 2];
        }

        if (t > 0) {
            if (wtid == 0) {
                const unsigned need = (unsigned)(t << 5);
                while (ld_acq(poll_ctr) < need) { }
            }
            barn(1 + hg);

            const char* src = (const char*)&g_h[d][t - 1][kb][0] + wtid * 16;
            uint32_t dst = hdst0;
#pragma unroll
            for (int i = 0; i < 8; i++) { cpa16(dst, src); dst += 2048; src += 2048; }
            cpa_commit();
#pragma unroll
            for (int i = 0; i < 8; i++) { cpa16(dst, src); dst += 2048; src += 2048; }
            cpa_commit();

            asm volatile("cp.async.wait_group 1;");
            barn(1 + hg);
#pragma unroll 8
            for (int k = 0; k < 64; k += 2) {
                ull hp0 = hl[k << 5], hp1 = hl[(k + 1) << 5];
                ulonglong2 q0 = wv0[k >> 1], q1 = wv1[k >> 1];
                ulonglong2 q2 = wv2[k >> 1], q3 = wv3[k >> 1];
                a0 = fma2(q0.x, hp0, a0); a0 = fma2(q0.y, hp1, a0);
                a1 = fma2(q1.x, hp0, a1); a1 = fma2(q1.y, hp1, a1);
                a2 = fma2(q2.x, hp0, a2); a2 = fma2(q2.y, hp1, a2);
                a3 = fma2(q3.x, hp0, a3); a3 = fma2(q3.y, hp1, a3);
            }
            asm volatile("cp.async.wait_group 0;");
            barn(1 + hg);
#pragma unroll 8
            for (int k = 64; k < 128; k += 2) {
                ull hp0 = hl[k << 5], hp1 = hl[(k + 1) << 5];
                ulonglong2 q0 = wv0[k >> 1], q1 = wv1[k >> 1];
                ulonglong2 q2 = wv2[k >> 1], q3 = wv3[k >> 1];
                a0 = fma2(q0.x, hp0, a0); a0 = fma2(q0.y, hp1, a0);
                a1 = fma2(q1.x, hp0, a1); a1 = fma2(q1.y, hp1, a1);
                a2 = fma2(q2.x, hp0, a2); a2 = fma2(q2.y, hp1, a2);
                a3 = fma2(q3.x, hp0, a3); a3 = fma2(q3.y, hp1, a3);
            }
            if (hg == 1) {
                red[       wtid] = a0; red[128 + wtid] = a1;
                red[256 + wtid] = a2; red[384 + wtid] = a3;
            }
        }
        __syncthreads();                       // sync1: wg1 partials visible
        ull r0 = 0, r1 = 0, r2 = 0, r3 = 0;
        if (hg == 0 && t > 0) {
            r0 = red[wtid]; r1 = red[128 + wtid];
            r2 = red[256 + wtid]; r3 = red[384 + wtid];
        }
        __syncthreads();                       // sync2: red consumed

        if (hg == 0) {
            if (t > 0) { a0 = add2(a0, r0); a1 = add2(a1, r1);
                         a2 = add2(a2, r2); a3 = add2(a3, r3); }
            float i0,i1,f0,f1,gg0,gg1,o0,o1;
            unpack2(a0,i0,i1); unpack2(a1,f0,f1); unpack2(a2,gg0,gg1); unpack2(a3,o0,o1);
            c0 = fsig(f0)*c0 + fsig(i0)*ftanh(gg0);
            c1 = fsig(f1)*c1 + fsig(i1)*ftanh(gg1);
            float h0 = fsig(o0)*ftanh(c0);
            float h1 = fsig(o1)*ftanh(c1);
            *(ull*)&g_h[d][t][u][l * 2] = pack2(h0, h1);
            barn(1);                           // wg0 stores complete
            if (wtid == 0) red_rel(my_ctr, 1u);
        }
    }
}

// ===========================================================================
// K3: emissions.  grid T_LEN x 256 thr; thread = (b, u-quarter).
// ===========================================================================
__global__ void k_emis(const float* __restrict__ w_cls, const float* __restrict__ b_cls)
{
    __shared__ float wc[512][12];
    __shared__ float red[4][64][10];
    const int tid = threadIdx.x, t = blockIdx.x;

    for (int i = tid; i < LL * 512; i += 256) wc[i & 511][i >> 9] = w_cls[i];
    __syncthreads();

    const int b = tid & 63, qa = tid >> 6;
    const float* hp = (qa < 2) ? &g_h[0][t][qa * 128][0]
                               : &g_h[1][T_LEN - 1 - t][(qa - 2) * 128][0];
    float acc[LL];
#pragma unroll
    for (int ll = 0; ll < LL; ll++) acc[ll] = 0.f;
    for (int uu = 0; uu < 128; uu++) {
        float hv = hp[(uu << 6) + b];
        const float* wr = &wc[qa * 128 + uu][0];
#pragma unroll
        for (int ll = 0; ll < LL; ll++) acc[ll] += hv * wr[ll];
    }
#pragma unroll
    for (int ll = 0; ll < LL; ll++) red[qa][b][ll] = acc[ll];
    __syncthreads();
    if (tid < 64) {
#pragma unroll
        for (int ll = 0; ll < LL; ll++)
            g_em[tid][t][ll] = red[0][tid][ll] + red[1][tid][ll]
                             + red[2][tid][ll] + red[3][tid][ll] + b_cls[ll];
    }
}

// ===========================================================================
// K4: CRF numerator + forward per batch (one warp / batch).
// ===========================================================================
__global__ void k_crf(const int* __restrict__ labels, const int* __restrict__ mask,
                      const float* __restrict__ trans, const float* __restrict__ start,
                      const float* __restrict__ endv)
{
    const int warp = threadIdx.x >> 5, lane = threadIdx.x & 31;
    const int b = blockIdx.x * 8 + warp;
    if (b >= BB) return;
    const float NEG = -1e30f;
    const int* lab = labels + b * T_LEN;
    const int* msk = mask   + b * T_LEN;
    const float* em = &g_em[b][0][0];

    float numl = 0.f; int msum = 0;
    for (int t = lane; t < T_LEN; t += 32) msum += msk[t];
    for (int t = 1 + lane; t < T_LEN; t += 32) {
        float mf = (float)msk[t];
        numl += mf * (trans[lab[t - 1] * LL + lab[t]] + em[t * LL + lab[t]]);
    }
#pragma unroll
    for (int o = 16; o; o >>= 1) {
        numl += __shfl_xor_sync(0xFFFFFFFFu, numl, o);
        msum += __shfl_xor_sync(0xFFFFFFFFu, msum, o);
    }

    float trc[LL];
#pragma unroll
    for (int i = 0; i < LL; i++) trc[i] = (lane < LL) ? trans[i * LL + lane] : 0.f;
    float alpha = (lane < LL) ? start[lane] + em[lane] : NEG;

    for (int t = 1; t < T_LEN; t++) {
        float emj = (lane < LL) ? em[t * LL + lane] : 0.f;
        int   mt  = msk[t];
        float tv[LL], m = NEG;
#pragma unroll
        for (int i = 0; i < LL; i++) {
            float ai = __shfl_sync(0xFFFFFFFFu, alpha, i);
            tv[i] = ai + trc[i];
            m = fmaxf(m, tv[i]);
        }
        float ss = 0.f;
#pragma unroll
        for (int i = 0; i < LL; i++) ss += __expf(tv[i] - m);
        float nxt = m + __logf(ss) + emj;
        if (lane < LL && mt) alpha = nxt;
    }

    float v = (lane < LL) ? alpha + endv[lane] : NEG;
    float m = v;
#pragma unroll
    for (int o = 16; o; o >>= 1) m = fmaxf(m, __shfl_xor_sync(0xFFFFFFFFu, m, o));
    float sv = __expf(v - m);
#pragma unroll
    for (int o = 16; o; o >>= 1) sv += __shfl_xor_sync(0xFFFFFFFFu, sv, o);
    float logZ = m + __logf(sv);

    if (lane == 0) {
        float num = numl + start[lab[0]] + em[lab[0]] + endv[lab[msum - 1]];
        g_res[b] = num - logZ;
    }
}

__global__ void k_final(float* out)
{
    const int tid = threadIdx.x;
    float v = g_res[tid];
#pragma unroll
    for (int o = 16; o; o >>= 1) v += __shfl_xor_sync(0xFFFFFFFFu, v, o);
    __shared__ float sred[2];
    if ((tid & 31) == 0) sred[tid >> 5] = v;
    __syncthreads();
    if (tid == 0) out[0] = -(sred[0] + sred[1]) / 64.0f;
}

// ===========================================================================
extern "C" void kernel_launch(void* const* d_in, const int* in_sizes, int n_in,
                              void* d_out, int out_size)
{
    const int*   ids   = (const int*)  d_in[0];
    const int*   msk   = (const int*)  d_in[1];
    const int*   lab   = (const int*)  d_in[2];
    const float* emb   = (const float*)d_in[3];
    const float* wif   = (const float*)d_in[4];
    const float* whf   = (const float*)d_in[5];
    const float* bif   = (const float*)d_in[6];
    const float* bhf   = (const float*)d_in[7];
    const float* wib   = (const float*)d_in[8];
    const float* whb   = (const float*)d_in[9];
    const float* bib   = (const float*)d_in[10];
    const float* bhb   = (const float*)d_in[11];
    const float* wcls  = (const float*)d_in[12];
    const float* bcls  = (const float*)d_in[13];
    const float* trans = (const float*)d_in[14];
    const float* start = (const float*)d_in[15];
    const float* endv  = (const float*)d_in[16];

    cudaFuncSetAttribute(k_lstm, cudaFuncAttributeMaxDynamicSharedMemorySize, 102400);

    k_xg  <<<dim3(8, T_LEN, 2), 256>>>(ids, emb, wif, bif, bhf, wib, bib, bhb);
    k_lstm<<<NCTA, 256, 102400>>>(whf, whb);
    k_emis<<<T_LEN, 256>>>(wcls, bcls);
    k_crf <<<8, 256>>>(lab, msk, trans, start, endv);
    k_final<<<1, 64>>>((float*)d_out);
}